// round 4
// baseline (speedup 1.0000x reference)
#include <cuda_runtime.h>
#include <math.h>

// Problem constants (fixed by the reference problem setup)
#define B_  8
#define N_  1000
#define V_  10000
#define H_  256
#define NA_ 37
#define NB_ 26

#define CPW 4                  // contacts per warp
#define CTA_PER_B 32           // 8 warps * 4 contacts = 32 contacts/CTA; 32 CTAs cover 1000 (+24 pad)

// exp(-d2/4.5) = exp2(d2 * CEXP),  CEXP = -1/(4.5*ln2)
#define CEXP      (-0.32059889f)
#define DEG2RAD_  (0.017453292519943295f)
#define SPREAD_   (0.3849001794597505f)   // sqrt(100/675)
#define SCALED_   (2.8444444444444446f)   // 256/90

// ---- scratch (no allocations allowed) ----
__device__ float  g_map[B_ * H_ * H_];
__device__ float  g_prep[B_][16];   // R[9], center[3], shank, mean_x, mean_y, mean_z
__device__ float4 g_v4[V_];         // vx, vy, vz, CEXP*|v|^2
__device__ float2 g_pe[V_];         // pol, ecc

__device__ __forceinline__ float fast_exp2(float x) {
    float y;
    asm("ex2.approx.f32 %0, %1;" : "=f"(y) : "f"(x));
    return y;
}

// ---------------------------------------------------------------------------
// Kernel 0: zero the accumulation maps (g_map persists across graph replays).
// ---------------------------------------------------------------------------
__global__ void zero_kernel() {
    int i = blockIdx.x * blockDim.x + threadIdx.x;   // over float4s
    reinterpret_cast<float4*>(g_map)[i] = make_float4(0.f, 0.f, 0.f, 0.f);
}

// ---------------------------------------------------------------------------
// Kernel 1: pack v1 data into vectorized SoA with pre-folded constants.
// ---------------------------------------------------------------------------
__global__ void soa_kernel(const float* __restrict__ v1_pos,
                           const float* __restrict__ v1_prf) {
    int v = blockIdx.x * blockDim.x + threadIdx.x;
    if (v >= V_) return;
    float x = v1_pos[3 * v + 0];
    float y = v1_pos[3 * v + 1];
    float z = v1_pos[3 * v + 2];
    g_v4[v] = make_float4(x, y, z, CEXP * (x * x + y * y + z * z));
    g_pe[v] = make_float2(v1_prf[3 * v + 0], v1_prf[3 * v + 1]);
}

// ---------------------------------------------------------------------------
// Kernel 2: per-batch prep (template means, rotation, LUT interp, grid center).
// ---------------------------------------------------------------------------
__global__ void prep_kernel(const float* __restrict__ params,
                            const float* __restrict__ start_loc,
                            const float* __restrict__ lut,
                            const float* __restrict__ agrid,
                            const float* __restrict__ bgrid,
                            const float* __restrict__ tmpl) {
    __shared__ float sx[256], sy[256], sz[256];
    __shared__ float means[3];
    int t = threadIdx.x;

    float ax = 0.f, ay = 0.f, az = 0.f;
    for (int n = t; n < N_; n += 256) {
        ax += tmpl[3 * n + 0];
        ay += tmpl[3 * n + 1];
        az += tmpl[3 * n + 2];
    }
    sx[t] = ax; sy[t] = ay; sz[t] = az;
    __syncthreads();
    for (int off = 128; off > 0; off >>= 1) {
        if (t < off) { sx[t] += sx[t + off]; sy[t] += sy[t + off]; sz[t] += sz[t + off]; }
        __syncthreads();
    }
    if (t == 0) {
        means[0] = sx[0] / (float)N_;
        means[1] = sy[0] / (float)N_;
        means[2] = sz[0] / (float)N_;
    }
    __syncthreads();

    if (t < B_) {
        int b = t;
        float alpha  = params[4 * b + 0];
        float beta   = params[4 * b + 1];
        float offset = params[4 * b + 2];
        float shank  = params[4 * b + 3];

        float a = alpha * DEG2RAD_, be = beta * DEG2RAD_;
        float ca = cosf(a), sa = sinf(a);
        float cb = cosf(be), sb = sinf(be);
        // R = Rx @ Ry
        float R00 = cb,       R01 = 0.f, R02 = sb;
        float R10 = sa * sb,  R11 = ca,  R12 = -sa * cb;
        float R20 = -ca * sb, R21 = sa,  R22 = ca * cb;

        // direction = R @ (0,0,-1), normalized
        float dx = -R02, dy = -R12, dz = -R22;
        float inv = rsqrtf(dx * dx + dy * dy + dz * dz);
        dx *= inv; dy *= inv; dz *= inv;

        // bilinear LUT interp (replicates reference arithmetic)
        float ag0 = agrid[0], agN = agrid[NA_ - 1];
        float bg0 = bgrid[0], bgN = bgrid[NB_ - 1];
        float an = 2.f * (alpha - ag0) / (agN - ag0 + 1e-8f) - 1.f;
        float bn = 2.f * (beta  - bg0) / (bgN - bg0 + 1e-8f) - 1.f;
        float ai = fminf(fmaxf((an + 1.f) * 0.5f * (NA_ - 1), 0.f), (float)(NA_ - 1));
        float bi = fminf(fmaxf((bn + 1.f) * 0.5f * (NB_ - 1), 0.f), (float)(NB_ - 1));
        int a0 = min(max((int)floorf(ai), 0), NA_ - 1);
        int b0 = min(max((int)floorf(bi), 0), NB_ - 1);
        int a1 = min(a0 + 1, NA_ - 1);
        int b1 = min(b0 + 1, NB_ - 1);
        float fa = ai - (float)a0, fb = bi - (float)b0;
        float v00 = lut[a0 * NB_ + b0], v01 = lut[a0 * NB_ + b1];
        float v10 = lut[a1 * NB_ + b0], v11 = lut[a1 * NB_ + b1];
        float surf = v00 * (1.f - fa) * (1.f - fb) + v01 * (1.f - fa) * fb
                   + v10 * fa * (1.f - fb)         + v11 * fa * fb;
        surf = fmaxf(surf, 1.f);

        float pen = surf - shank * 0.5f - offset;
        float c0 = start_loc[0] + dx * pen;
        float c1 = start_loc[1] + dy * pen;
        float c2 = start_loc[2] + dz * pen;

        float* P = g_prep[b];
        P[0] = R00; P[1] = R01; P[2] = R02;
        P[3] = R10; P[4] = R11; P[5] = R12;
        P[6] = R20; P[7] = R21; P[8] = R22;
        P[9] = c0;  P[10] = c1; P[11] = c2;
        P[12] = shank; P[13] = means[0]; P[14] = means[1]; P[15] = means[2];
    }
}

// ---------------------------------------------------------------------------
// Kernel 3: fused soft-match + windowed gaussian scatter.
// Each warp handles CPW=4 contacts, amortizing the V-stream loads 4x.
// ---------------------------------------------------------------------------
__global__ void __launch_bounds__(256) match_kernel(const float* __restrict__ tmpl,
                                                    const float* __restrict__ logits) {
    int warp = threadIdx.x >> 5;
    int lane = threadIdx.x & 31;
    int b = blockIdx.x >> 5;                       // 32 CTAs per batch
    int cta = blockIdx.x & 31;
    int n0 = (cta * 8 + warp) * CPW;               // first contact for this warp

    const float* P = g_prep[b];
    float R00 = P[0], R01 = P[1], R02 = P[2];
    float R10 = P[3], R11 = P[4], R12 = P[5];
    float R20 = P[6], R21 = P[7], R22 = P[8];
    float c0 = P[9], c1 = P[10], c2 = P[11];
    float shank = P[12], mx = P[13], my = P[14], mz = P[15];

    float cp2[CPW], ax[CPW], ay[CPW], az[CPW];
    bool valid[CPW];
    #pragma unroll
    for (int k = 0; k < CPW; k++) {
        int n = n0 + k;
        valid[k] = (n < N_);
        int nc = valid[k] ? n : (N_ - 1);
        float tx = tmpl[3 * nc + 0] - mx;
        float ty = tmpl[3 * nc + 1] - my;
        float tz = (tmpl[3 * nc + 2] - mz) * shank;
        float px = fmaf(R00, tx, fmaf(R01, ty, R02 * tz)) + c0;
        float py = fmaf(R10, tx, fmaf(R11, ty, R12 * tz)) + c1;
        float pz = fmaf(R20, tx, fmaf(R21, ty, R22 * tz)) + c2;
        cp2[k] = CEXP * (px * px + py * py + pz * pz);
        ax[k] = -2.f * CEXP * px;
        ay[k] = -2.f * CEXP * py;
        az[k] = -2.f * CEXP * pz;
    }

    float wsum[CPW], spol[CPW], secc[CPW];
    #pragma unroll
    for (int k = 0; k < CPW; k++) { wsum[k] = 0.f; spol[k] = 0.f; secc[k] = 0.f; }

    #pragma unroll 2
    for (int v = lane; v < V_; v += 32) {
        float4 q  = g_v4[v];
        float2 pe = g_pe[v];
        #pragma unroll
        for (int k = 0; k < CPW; k++) {
            float arg = q.w + cp2[k];
            arg = fmaf(q.z, az[k], arg);
            arg = fmaf(q.y, ay[k], arg);
            arg = fmaf(q.x, ax[k], arg);
            float w = fast_exp2(arg);              // exp(-d2/4.5)
            wsum[k] += w;
            spol[k] = fmaf(w, pe.x, spol[k]);
            secc[k] = fmaf(w, pe.y, secc[k]);
        }
    }

    #pragma unroll
    for (int o = 16; o > 0; o >>= 1) {
        #pragma unroll
        for (int k = 0; k < CPW; k++) {
            wsum[k] += __shfl_xor_sync(0xffffffffu, wsum[k], o);
            spol[k] += __shfl_xor_sync(0xffffffffu, spol[k], o);
            secc[k] += __shfl_xor_sync(0xffffffffu, secc[k], o);
        }
    }

    float* mp = g_map + b * (H_ * H_);

    #pragma unroll
    for (int k = 0; k < CPW; k++) {
        if (!valid[k]) continue;
        float inv = 1.f / (wsum[k] + 1e-8f);
        float pol = spol[k] * inv;
        float ecc = secc[k] * inv;
        float ang = pol * DEG2RAD_;
        float m = 17.3f * (1.f / (ecc + 0.75f) - 1.f / (ecc + 120.0f));
        float m_inv = 1.f / (fabsf(m) + 1e-8f);
        float psig = SPREAD_ * m_inv * 0.5f;
        float sv, cv;
        sincosf(ang, &sv, &cv);
        float cxp = ecc * cv * SCALED_ + 128.0f;
        float cyp = ecc * sv * SCALED_ + 128.0f;
        float size = fmaxf(psig * SCALED_, 1.0f);
        float validity = fminf(wsum[k], 1.0f);
        float lg = logits[b * N_ + n0 + k];
        float wf = validity / (1.f + __expf(-lg));

        // gaussian window scatter: beyond 6*size the tail < exp(-36) ~ 2e-16,
        // below fp32 resolution of the summed map.
        float rad = 6.0f * size;
        int x0 = max(0, (int)ceilf(cxp - rad));
        int x1 = min(H_ - 1, (int)floorf(cxp + rad));
        int y0 = max(0, (int)ceilf(cyp - rad));
        int y1 = min(H_ - 1, (int)floorf(cyp + rad));
        int wx = x1 - x0 + 1;
        int wy = y1 - y0 + 1;
        if (wx <= 0 || wy <= 0) continue;
        int tot = wx * wy;
        float kk = -1.44269504f / (size * size + 1e-8f);   // exp2 folding
        for (int p = lane; p < tot; p += 32) {
            int j = x0 + p % wx;
            int i = y0 + p / wx;
            float dx = (float)j - cxp;
            float dy = (float)i - cyp;
            float val = wf * fast_exp2(fmaf(dx, dx, dy * dy) * kk);
            atomicAdd(mp + i * H_ + j, val);
        }
    }
}

// ---------------------------------------------------------------------------
// Kernel 4: per-batch max, then rot90(k=1) + normalize into d_out.
// out[b,0,i,j] = map[b, j, 255-i] / (max + 1e-8)
// ---------------------------------------------------------------------------
__global__ void finish_kernel(float* __restrict__ out) {
    int b = blockIdx.x;
    const float* mp = g_map + b * (H_ * H_);
    __shared__ float sred[8];
    int t = threadIdx.x;
    int lane = t & 31, warp = t >> 5;

    float mx = 0.f;    // map values are non-negative
    for (int i = t; i < H_ * H_; i += 256) mx = fmaxf(mx, mp[i]);
    #pragma unroll
    for (int o = 16; o > 0; o >>= 1) mx = fmaxf(mx, __shfl_xor_sync(0xffffffffu, mx, o));
    if (lane == 0) sred[warp] = mx;
    __syncthreads();
    if (t == 0) {
        float m2 = sred[0];
        #pragma unroll
        for (int k = 1; k < 8; k++) m2 = fmaxf(m2, sred[k]);
        sred[0] = m2;
    }
    __syncthreads();
    float invm = 1.f / (sred[0] + 1e-8f);

    float* ob = out + b * (H_ * H_);
    for (int p = t; p < H_ * H_; p += 256) {
        int i = p >> 8;
        int j = p & 255;
        ob[p] = mp[j * H_ + (H_ - 1 - i)] * invm;
    }
}

// ---------------------------------------------------------------------------
// Input order (metadata): params, electrode_logits, v1_pos, v1_prf, start_loc,
//                         surf_dist_lut, alpha_grid, beta_grid, grid_template
// ---------------------------------------------------------------------------
extern "C" void kernel_launch(void* const* d_in, const int* in_sizes, int n_in,
                              void* d_out, int out_size) {
    const float* params   = (const float*)d_in[0];
    const float* logits   = (const float*)d_in[1];
    const float* v1_pos   = (const float*)d_in[2];
    const float* v1_prf   = (const float*)d_in[3];
    const float* startloc = (const float*)d_in[4];
    const float* lut      = (const float*)d_in[5];
    const float* agrid    = (const float*)d_in[6];
    const float* bgrid    = (const float*)d_in[7];
    const float* tmpl     = (const float*)d_in[8];
    float* out = (float*)d_out;

    zero_kernel<<<(B_ * H_ * H_ / 4) / 256, 256>>>();
    soa_kernel<<<(V_ + 255) / 256, 256>>>(v1_pos, v1_prf);
    prep_kernel<<<1, 256>>>(params, startloc, lut, agrid, bgrid, tmpl);
    match_kernel<<<B_ * CTA_PER_B, 256>>>(tmpl, logits);
    finish_kernel<<<B_, 256>>>(out);
}

// round 6
// speedup vs baseline: 1.7700x; 1.7700x over previous
#include <cuda_runtime.h>
#include <math.h>

// Problem constants (fixed by the reference problem setup)
#define B_  8
#define N_  1000
#define V_  10000
#define H_  256
#define NA_ 37
#define NB_ 26

#define CPW 4                  // contacts per warp
#define VS_ 4                  // V-dimension splits (restores grid occupancy)
#define VCHUNK (V_ / VS_)      // 2500
#define CTA_PER_B 32           // 8 warps * 4 contacts = 32 contacts/CTA
#define NPAD 1024              // padded contact count for scratch indexing

// exp(-d2/4.5) = exp2(d2 * CEXP),  CEXP = -1/(4.5*ln2)
#define CEXP      (-0.32059889f)
#define DEG2RAD_  (0.017453292519943295f)
#define SPREAD_   (0.3849001794597505f)   // sqrt(100/675)
#define SCALED_   (2.8444444444444446f)   // 256/90

// ---- scratch (no allocations allowed) ----
__device__ float  g_map[B_ * H_ * H_];
__device__ float  g_prep[B_][16];   // R[9], center[3], shank, mean_x, mean_y, mean_z
__device__ float4 g_v4[V_];         // vx, vy, vz, CEXP*|v|^2
__device__ float2 g_pe[V_];         // pol, ecc
// partial reductions: [vs][b][n] (written fully each launch; no zeroing needed)
__device__ float  g_pw[VS_ * B_ * NPAD];
__device__ float  g_pp[VS_ * B_ * NPAD];
__device__ float  g_pc[VS_ * B_ * NPAD];

__device__ __forceinline__ float fast_exp2(float x) {
    float y;
    asm("ex2.approx.f32 %0, %1;" : "=f"(y) : "f"(x));
    return y;
}

// ---------------------------------------------------------------------------
// Kernel 0: zero the accumulation maps (g_map persists across graph replays).
// ---------------------------------------------------------------------------
__global__ void zero_kernel() {
    int i = blockIdx.x * blockDim.x + threadIdx.x;   // over float4s
    reinterpret_cast<float4*>(g_map)[i] = make_float4(0.f, 0.f, 0.f, 0.f);
}

// ---------------------------------------------------------------------------
// Kernel 1: pack v1 data into vectorized SoA with pre-folded constants.
// ---------------------------------------------------------------------------
__global__ void soa_kernel(const float* __restrict__ v1_pos,
                           const float* __restrict__ v1_prf) {
    int v = blockIdx.x * blockDim.x + threadIdx.x;
    if (v >= V_) return;
    float x = v1_pos[3 * v + 0];
    float y = v1_pos[3 * v + 1];
    float z = v1_pos[3 * v + 2];
    g_v4[v] = make_float4(x, y, z, CEXP * (x * x + y * y + z * z));
    g_pe[v] = make_float2(v1_prf[3 * v + 0], v1_prf[3 * v + 1]);
}

// ---------------------------------------------------------------------------
// Kernel 2: per-batch prep (template means, rotation, LUT interp, grid center).
// ---------------------------------------------------------------------------
__global__ void prep_kernel(const float* __restrict__ params,
                            const float* __restrict__ start_loc,
                            const float* __restrict__ lut,
                            const float* __restrict__ agrid,
                            const float* __restrict__ bgrid,
                            const float* __restrict__ tmpl) {
    __shared__ float sx[256], sy[256], sz[256];
    __shared__ float means[3];
    int t = threadIdx.x;

    float ax = 0.f, ay = 0.f, az = 0.f;
    for (int n = t; n < N_; n += 256) {
        ax += tmpl[3 * n + 0];
        ay += tmpl[3 * n + 1];
        az += tmpl[3 * n + 2];
    }
    sx[t] = ax; sy[t] = ay; sz[t] = az;
    __syncthreads();
    for (int off = 128; off > 0; off >>= 1) {
        if (t < off) { sx[t] += sx[t + off]; sy[t] += sy[t + off]; sz[t] += sz[t + off]; }
        __syncthreads();
    }
    if (t == 0) {
        means[0] = sx[0] / (float)N_;
        means[1] = sy[0] / (float)N_;
        means[2] = sz[0] / (float)N_;
    }
    __syncthreads();

    if (t < B_) {
        int b = t;
        float alpha  = params[4 * b + 0];
        float beta   = params[4 * b + 1];
        float offset = params[4 * b + 2];
        float shank  = params[4 * b + 3];

        float a = alpha * DEG2RAD_, be = beta * DEG2RAD_;
        float ca = cosf(a), sa = sinf(a);
        float cb = cosf(be), sb = sinf(be);
        // R = Rx @ Ry
        float R00 = cb,       R01 = 0.f, R02 = sb;
        float R10 = sa * sb,  R11 = ca,  R12 = -sa * cb;
        float R20 = -ca * sb, R21 = sa,  R22 = ca * cb;

        // direction = R @ (0,0,-1), normalized
        float dx = -R02, dy = -R12, dz = -R22;
        float inv = rsqrtf(dx * dx + dy * dy + dz * dz);
        dx *= inv; dy *= inv; dz *= inv;

        // bilinear LUT interp (replicates reference arithmetic)
        float ag0 = agrid[0], agN = agrid[NA_ - 1];
        float bg0 = bgrid[0], bgN = bgrid[NB_ - 1];
        float an = 2.f * (alpha - ag0) / (agN - ag0 + 1e-8f) - 1.f;
        float bn = 2.f * (beta  - bg0) / (bgN - bg0 + 1e-8f) - 1.f;
        float ai = fminf(fmaxf((an + 1.f) * 0.5f * (NA_ - 1), 0.f), (float)(NA_ - 1));
        float bi = fminf(fmaxf((bn + 1.f) * 0.5f * (NB_ - 1), 0.f), (float)(NB_ - 1));
        int a0 = min(max((int)floorf(ai), 0), NA_ - 1);
        int b0 = min(max((int)floorf(bi), 0), NB_ - 1);
        int a1 = min(a0 + 1, NA_ - 1);
        int b1 = min(b0 + 1, NB_ - 1);
        float fa = ai - (float)a0, fb = bi - (float)b0;
        float v00 = lut[a0 * NB_ + b0], v01 = lut[a0 * NB_ + b1];
        float v10 = lut[a1 * NB_ + b0], v11 = lut[a1 * NB_ + b1];
        float surf = v00 * (1.f - fa) * (1.f - fb) + v01 * (1.f - fa) * fb
                   + v10 * fa * (1.f - fb)         + v11 * fa * fb;
        surf = fmaxf(surf, 1.f);

        float pen = surf - shank * 0.5f - offset;
        float c0 = start_loc[0] + dx * pen;
        float c1 = start_loc[1] + dy * pen;
        float c2 = start_loc[2] + dz * pen;

        float* P = g_prep[b];
        P[0] = R00; P[1] = R01; P[2] = R02;
        P[3] = R10; P[4] = R11; P[5] = R12;
        P[6] = R20; P[7] = R21; P[8] = R22;
        P[9] = c0;  P[10] = c1; P[11] = c2;
        P[12] = shank; P[13] = means[0]; P[14] = means[1]; P[15] = means[2];
    }
}

// ---------------------------------------------------------------------------
// Kernel 3a: soft-match partial sums.
// grid = VS_ * B_ * CTA_PER_B CTAs (1024). Each warp: CPW=4 contacts over a
// V-chunk of 2500 elements. Partials stored deterministically per split.
// ---------------------------------------------------------------------------
__global__ void __launch_bounds__(256) match_part_kernel(const float* __restrict__ tmpl) {
    int warp = threadIdx.x >> 5;
    int lane = threadIdx.x & 31;
    int cta  = blockIdx.x & 31;          // 32 CTAs per (vs, b)
    int b    = (blockIdx.x >> 5) & 7;
    int vs   = blockIdx.x >> 8;
    int n0   = (cta * 8 + warp) * CPW;   // first contact for this warp

    const float* P = g_prep[b];
    float R00 = P[0], R01 = P[1], R02 = P[2];
    float R10 = P[3], R11 = P[4], R12 = P[5];
    float R20 = P[6], R21 = P[7], R22 = P[8];
    float c0 = P[9], c1 = P[10], c2 = P[11];
    float shank = P[12], mx = P[13], my = P[14], mz = P[15];

    float cp2[CPW], ax[CPW], ay[CPW], az[CPW];
    #pragma unroll
    for (int k = 0; k < CPW; k++) {
        int n = n0 + k;
        int nc = (n < N_) ? n : (N_ - 1);
        float tx = tmpl[3 * nc + 0] - mx;
        float ty = tmpl[3 * nc + 1] - my;
        float tz = (tmpl[3 * nc + 2] - mz) * shank;
        float px = fmaf(R00, tx, fmaf(R01, ty, R02 * tz)) + c0;
        float py = fmaf(R10, tx, fmaf(R11, ty, R12 * tz)) + c1;
        float pz = fmaf(R20, tx, fmaf(R21, ty, R22 * tz)) + c2;
        cp2[k] = CEXP * (px * px + py * py + pz * pz);
        ax[k] = -2.f * CEXP * px;
        ay[k] = -2.f * CEXP * py;
        az[k] = -2.f * CEXP * pz;
    }

    float wsum[CPW], spol[CPW], secc[CPW];
    #pragma unroll
    for (int k = 0; k < CPW; k++) { wsum[k] = 0.f; spol[k] = 0.f; secc[k] = 0.f; }

    int vend = vs * VCHUNK + VCHUNK;
    #pragma unroll 2
    for (int v = vs * VCHUNK + lane; v < vend; v += 32) {
        float4 q  = g_v4[v];
        float2 pe = g_pe[v];
        #pragma unroll
        for (int k = 0; k < CPW; k++) {
            float arg = q.w + cp2[k];
            arg = fmaf(q.z, az[k], arg);
            arg = fmaf(q.y, ay[k], arg);
            arg = fmaf(q.x, ax[k], arg);
            float w = fast_exp2(arg);              // exp(-d2/4.5)
            wsum[k] += w;
            spol[k] = fmaf(w, pe.x, spol[k]);
            secc[k] = fmaf(w, pe.y, secc[k]);
        }
    }

    #pragma unroll
    for (int o = 16; o > 0; o >>= 1) {
        #pragma unroll
        for (int k = 0; k < CPW; k++) {
            wsum[k] += __shfl_xor_sync(0xffffffffu, wsum[k], o);
            spol[k] += __shfl_xor_sync(0xffffffffu, spol[k], o);
            secc[k] += __shfl_xor_sync(0xffffffffu, secc[k], o);
        }
    }

    if (lane < CPW) {
        int k = lane;
        int n = n0 + k;
        if (n < N_) {
            int idx = (vs * B_ + b) * NPAD + n;
            // pull k-th accumulator from lane 0's registers? no — after the
            // xor-reduction every lane holds the full sum, so lane k can store k.
            g_pw[idx] = wsum[k];
            g_pp[idx] = spol[k];
            g_pc[idx] = secc[k];
        }
    }
}

// ---------------------------------------------------------------------------
// Kernel 3b: combine partials, compute phosphene params, windowed scatter.
// One warp per contact; grid = B_ * 125 CTAs of 8 warps.
// ---------------------------------------------------------------------------
__global__ void __launch_bounds__(256) scatter_kernel(const float* __restrict__ logits) {
    int warp = threadIdx.x >> 5;
    int lane = threadIdx.x & 31;
    int b = blockIdx.x / 125;
    int n = (blockIdx.x % 125) * 8 + warp;

    float wsum = 0.f, spol = 0.f, secc = 0.f;
    #pragma unroll
    for (int vs = 0; vs < VS_; vs++) {
        int idx = (vs * B_ + b) * NPAD + n;
        wsum += g_pw[idx];
        spol += g_pp[idx];
        secc += g_pc[idx];
    }

    float inv = 1.f / (wsum + 1e-8f);
    float pol = spol * inv;
    float ecc = secc * inv;
    float ang = pol * DEG2RAD_;
    float m = 17.3f * (1.f / (ecc + 0.75f) - 1.f / (ecc + 120.0f));
    float m_inv = 1.f / (fabsf(m) + 1e-8f);
    float psig = SPREAD_ * m_inv * 0.5f;
    float sv, cv;
    sincosf(ang, &sv, &cv);
    float cxp = ecc * cv * SCALED_ + 128.0f;
    float cyp = ecc * sv * SCALED_ + 128.0f;
    float size = fmaxf(psig * SCALED_, 1.0f);
    float validity = fminf(wsum, 1.0f);
    float lg = logits[b * N_ + n];
    float wf = validity / (1.f + __expf(-lg));

    // gaussian window scatter: beyond 6*size the tail < exp(-36) ~ 2e-16,
    // below fp32 resolution of the summed map.
    float rad = 6.0f * size;
    int x0 = max(0, (int)ceilf(cxp - rad));
    int x1 = min(H_ - 1, (int)floorf(cxp + rad));
    int y0 = max(0, (int)ceilf(cyp - rad));
    int y1 = min(H_ - 1, (int)floorf(cyp + rad));
    int wx = x1 - x0 + 1;
    int wy = y1 - y0 + 1;
    if (wx <= 0 || wy <= 0) return;
    int tot = wx * wy;
    float kk = -1.44269504f / (size * size + 1e-8f);   // exp2 folding
    float* mp = g_map + b * (H_ * H_);
    for (int p = lane; p < tot; p += 32) {
        int j = x0 + p % wx;
        int i = y0 + p / wx;
        float dx = (float)j - cxp;
        float dy = (float)i - cyp;
        float val = wf * fast_exp2(fmaf(dx, dx, dy * dy) * kk);
        atomicAdd(mp + i * H_ + j, val);
    }
}

// ---------------------------------------------------------------------------
// Kernel 4: per-batch max, then rot90(k=1) + normalize into d_out.
// out[b,0,i,j] = map[b, j, 255-i] / (max + 1e-8)
// ---------------------------------------------------------------------------
__global__ void finish_kernel(float* __restrict__ out) {
    int b = blockIdx.x;
    const float* mp = g_map + b * (H_ * H_);
    __shared__ float sred[8];
    int t = threadIdx.x;
    int lane = t & 31, warp = t >> 5;

    float mx = 0.f;    // map values are non-negative
    for (int i = t; i < H_ * H_; i += 256) mx = fmaxf(mx, mp[i]);
    #pragma unroll
    for (int o = 16; o > 0; o >>= 1) mx = fmaxf(mx, __shfl_xor_sync(0xffffffffu, mx, o));
    if (lane == 0) sred[warp] = mx;
    __syncthreads();
    if (t == 0) {
        float m2 = sred[0];
        #pragma unroll
        for (int k = 1; k < 8; k++) m2 = fmaxf(m2, sred[k]);
        sred[0] = m2;
    }
    __syncthreads();
    float invm = 1.f / (sred[0] + 1e-8f);

    float* ob = out + b * (H_ * H_);
    for (int p = t; p < H_ * H_; p += 256) {
        int i = p >> 8;
        int j = p & 255;
        ob[p] = mp[j * H_ + (H_ - 1 - i)] * invm;
    }
}

// ---------------------------------------------------------------------------
// Input order (metadata): params, electrode_logits, v1_pos, v1_prf, start_loc,
//                         surf_dist_lut, alpha_grid, beta_grid, grid_template
// ---------------------------------------------------------------------------
extern "C" void kernel_launch(void* const* d_in, const int* in_sizes, int n_in,
                              void* d_out, int out_size) {
    const float* params   = (const float*)d_in[0];
    const float* logits   = (const float*)d_in[1];
    const float* v1_pos   = (const float*)d_in[2];
    const float* v1_prf   = (const float*)d_in[3];
    const float* startloc = (const float*)d_in[4];
    const float* lut      = (const float*)d_in[5];
    const float* agrid    = (const float*)d_in[6];
    const float* bgrid    = (const float*)d_in[7];
    const float* tmpl     = (const float*)d_in[8];
    float* out = (float*)d_out;

    zero_kernel<<<(B_ * H_ * H_ / 4) / 256, 256>>>();
    soa_kernel<<<(V_ + 255) / 256, 256>>>(v1_pos, v1_prf);
    prep_kernel<<<1, 256>>>(params, startloc, lut, agrid, bgrid, tmpl);
    match_part_kernel<<<VS_ * B_ * CTA_PER_B, 256>>>(tmpl);
    scatter_kernel<<<B_ * 125, 256>>>(logits);
    finish_kernel<<<B_, 256>>>(out);
}

// round 7
// speedup vs baseline: 2.1985x; 1.2421x over previous
#include <cuda_runtime.h>
#include <math.h>

// Problem constants (fixed by the reference problem setup)
#define B_  8
#define N_  1000
#define V_  10000
#define H_  256
#define NA_ 37
#define NB_ 26

#define CPW 4                  // contacts per warp
#define VS_ 4                  // V-dimension splits (restores grid occupancy)
#define VCHUNK (V_ / VS_)      // 2500
#define CTA_PER_B 32           // 8 warps * 4 contacts = 32 contacts/CTA
#define NPAD 1024              // padded contact count for scratch indexing

// exp(-d2/4.5) = exp2(d2 * CEXP),  CEXP = -1/(4.5*ln2)
#define CEXP      (-0.32059889f)
#define DEG2RAD_  (0.017453292519943295f)
#define SPREAD_   (0.3849001794597505f)   // sqrt(100/675)
#define SCALED_   (2.8444444444444446f)   // 256/90

// ---- scratch (no allocations allowed) ----
__device__ float  g_map[B_ * H_ * H_];
__device__ float  g_prep[B_][16];   // R[9], center[3], shank, mean_x, mean_y, mean_z
__device__ float4 g_v4[V_];         // vx, vy, vz, CEXP*|v|^2
__device__ float2 g_pe[V_];         // pol, ecc
__device__ float  g_bmax[B_];       // per-batch map max (float bits via atomicMax int)
// partial reductions: [vs][b][n] (written fully each launch; no zeroing needed)
__device__ float  g_pw[VS_ * B_ * NPAD];
__device__ float  g_pp[VS_ * B_ * NPAD];
__device__ float  g_pc[VS_ * B_ * NPAD];

__device__ __forceinline__ float fast_exp2(float x) {
    float y;
    asm("ex2.approx.f32 %0, %1;" : "=f"(y) : "f"(x));
    return y;
}

// ---------------------------------------------------------------------------
// Kernel 0 (merged init):
//   blocks 0..511 : zero g_map (float4 granularity); block 0 zeros g_bmax
//   blocks 0..39  : also pack v1 SoA (40*256 >= 10000)
//   block  512    : per-batch prep (means, rotation, LUT, grid center)
// ---------------------------------------------------------------------------
__global__ void init_kernel(const float* __restrict__ v1_pos,
                            const float* __restrict__ v1_prf,
                            const float* __restrict__ params,
                            const float* __restrict__ start_loc,
                            const float* __restrict__ lut,
                            const float* __restrict__ agrid,
                            const float* __restrict__ bgrid,
                            const float* __restrict__ tmpl) {
    int blk = blockIdx.x;
    int t   = threadIdx.x;

    if (blk < 512) {
        // ---- zero map ----
        int i = blk * 256 + t;
        reinterpret_cast<float4*>(g_map)[i] = make_float4(0.f, 0.f, 0.f, 0.f);
        if (blk == 0 && t < B_) g_bmax[t] = 0.f;

        // ---- SoA pack ----
        int v = blk * 256 + t;
        if (v < V_) {
            float x = v1_pos[3 * v + 0];
            float y = v1_pos[3 * v + 1];
            float z = v1_pos[3 * v + 2];
            g_v4[v] = make_float4(x, y, z, CEXP * (x * x + y * y + z * z));
            g_pe[v] = make_float2(v1_prf[3 * v + 0], v1_prf[3 * v + 1]);
        }
        return;
    }

    // ---- prep (block 512) ----
    __shared__ float sx[256], sy[256], sz[256];
    __shared__ float means[3];

    float ax = 0.f, ay = 0.f, az = 0.f;
    for (int n = t; n < N_; n += 256) {
        ax += tmpl[3 * n + 0];
        ay += tmpl[3 * n + 1];
        az += tmpl[3 * n + 2];
    }
    sx[t] = ax; sy[t] = ay; sz[t] = az;
    __syncthreads();
    for (int off = 128; off > 0; off >>= 1) {
        if (t < off) { sx[t] += sx[t + off]; sy[t] += sy[t + off]; sz[t] += sz[t + off]; }
        __syncthreads();
    }
    if (t == 0) {
        means[0] = sx[0] / (float)N_;
        means[1] = sy[0] / (float)N_;
        means[2] = sz[0] / (float)N_;
    }
    __syncthreads();

    if (t < B_) {
        int b = t;
        float alpha  = params[4 * b + 0];
        float beta   = params[4 * b + 1];
        float offset = params[4 * b + 2];
        float shank  = params[4 * b + 3];

        float a = alpha * DEG2RAD_, be = beta * DEG2RAD_;
        float ca = cosf(a), sa = sinf(a);
        float cb = cosf(be), sb = sinf(be);
        // R = Rx @ Ry
        float R00 = cb,       R01 = 0.f, R02 = sb;
        float R10 = sa * sb,  R11 = ca,  R12 = -sa * cb;
        float R20 = -ca * sb, R21 = sa,  R22 = ca * cb;

        // direction = R @ (0,0,-1), normalized
        float dx = -R02, dy = -R12, dz = -R22;
        float inv = rsqrtf(dx * dx + dy * dy + dz * dz);
        dx *= inv; dy *= inv; dz *= inv;

        // bilinear LUT interp (replicates reference arithmetic)
        float ag0 = agrid[0], agN = agrid[NA_ - 1];
        float bg0 = bgrid[0], bgN = bgrid[NB_ - 1];
        float an = 2.f * (alpha - ag0) / (agN - ag0 + 1e-8f) - 1.f;
        float bn = 2.f * (beta  - bg0) / (bgN - bg0 + 1e-8f) - 1.f;
        float ai = fminf(fmaxf((an + 1.f) * 0.5f * (NA_ - 1), 0.f), (float)(NA_ - 1));
        float bi = fminf(fmaxf((bn + 1.f) * 0.5f * (NB_ - 1), 0.f), (float)(NB_ - 1));
        int a0 = min(max((int)floorf(ai), 0), NA_ - 1);
        int b0 = min(max((int)floorf(bi), 0), NB_ - 1);
        int a1 = min(a0 + 1, NA_ - 1);
        int b1 = min(b0 + 1, NB_ - 1);
        float fa = ai - (float)a0, fb = bi - (float)b0;
        float v00 = lut[a0 * NB_ + b0], v01 = lut[a0 * NB_ + b1];
        float v10 = lut[a1 * NB_ + b0], v11 = lut[a1 * NB_ + b1];
        float surf = v00 * (1.f - fa) * (1.f - fb) + v01 * (1.f - fa) * fb
                   + v10 * fa * (1.f - fb)         + v11 * fa * fb;
        surf = fmaxf(surf, 1.f);

        float pen = surf - shank * 0.5f - offset;
        float c0 = start_loc[0] + dx * pen;
        float c1 = start_loc[1] + dy * pen;
        float c2 = start_loc[2] + dz * pen;

        float* P = g_prep[b];
        P[0] = R00; P[1] = R01; P[2] = R02;
        P[3] = R10; P[4] = R11; P[5] = R12;
        P[6] = R20; P[7] = R21; P[8] = R22;
        P[9] = c0;  P[10] = c1; P[11] = c2;
        P[12] = shank; P[13] = means[0]; P[14] = means[1]; P[15] = means[2];
    }
}

// ---------------------------------------------------------------------------
// Kernel 1: soft-match partial sums.
// grid = VS_ * B_ * CTA_PER_B CTAs (1024). Each warp: CPW=4 contacts over a
// V-chunk of 2500 elements. Partials stored deterministically per split.
// ---------------------------------------------------------------------------
__global__ void __launch_bounds__(256) match_part_kernel(const float* __restrict__ tmpl) {
    int warp = threadIdx.x >> 5;
    int lane = threadIdx.x & 31;
    int cta  = blockIdx.x & 31;          // 32 CTAs per (vs, b)
    int b    = (blockIdx.x >> 5) & 7;
    int vs   = blockIdx.x >> 8;
    int n0   = (cta * 8 + warp) * CPW;   // first contact for this warp

    const float* P = g_prep[b];
    float R00 = P[0], R01 = P[1], R02 = P[2];
    float R10 = P[3], R11 = P[4], R12 = P[5];
    float R20 = P[6], R21 = P[7], R22 = P[8];
    float c0 = P[9], c1 = P[10], c2 = P[11];
    float shank = P[12], mx = P[13], my = P[14], mz = P[15];

    float cp2[CPW], ax[CPW], ay[CPW], az[CPW];
    #pragma unroll
    for (int k = 0; k < CPW; k++) {
        int n = n0 + k;
        int nc = (n < N_) ? n : (N_ - 1);
        float tx = tmpl[3 * nc + 0] - mx;
        float ty = tmpl[3 * nc + 1] - my;
        float tz = (tmpl[3 * nc + 2] - mz) * shank;
        float px = fmaf(R00, tx, fmaf(R01, ty, R02 * tz)) + c0;
        float py = fmaf(R10, tx, fmaf(R11, ty, R12 * tz)) + c1;
        float pz = fmaf(R20, tx, fmaf(R21, ty, R22 * tz)) + c2;
        cp2[k] = CEXP * (px * px + py * py + pz * pz);
        ax[k] = -2.f * CEXP * px;
        ay[k] = -2.f * CEXP * py;
        az[k] = -2.f * CEXP * pz;
    }

    float wsum[CPW], spol[CPW], secc[CPW];
    #pragma unroll
    for (int k = 0; k < CPW; k++) { wsum[k] = 0.f; spol[k] = 0.f; secc[k] = 0.f; }

    int vend = vs * VCHUNK + VCHUNK;
    #pragma unroll 2
    for (int v = vs * VCHUNK + lane; v < vend; v += 32) {
        float4 q  = g_v4[v];
        float2 pe = g_pe[v];
        #pragma unroll
        for (int k = 0; k < CPW; k++) {
            float arg = q.w + cp2[k];
            arg = fmaf(q.z, az[k], arg);
            arg = fmaf(q.y, ay[k], arg);
            arg = fmaf(q.x, ax[k], arg);
            float w = fast_exp2(arg);              // exp(-d2/4.5)
            wsum[k] += w;
            spol[k] = fmaf(w, pe.x, spol[k]);
            secc[k] = fmaf(w, pe.y, secc[k]);
        }
    }

    #pragma unroll
    for (int o = 16; o > 0; o >>= 1) {
        #pragma unroll
        for (int k = 0; k < CPW; k++) {
            wsum[k] += __shfl_xor_sync(0xffffffffu, wsum[k], o);
            spol[k] += __shfl_xor_sync(0xffffffffu, spol[k], o);
            secc[k] += __shfl_xor_sync(0xffffffffu, secc[k], o);
        }
    }

    if (lane < CPW) {
        int k = lane;
        int n = n0 + k;
        if (n < N_) {
            int idx = (vs * B_ + b) * NPAD + n;
            g_pw[idx] = wsum[k];
            g_pp[idx] = spol[k];
            g_pc[idx] = secc[k];
        }
    }
}

// ---------------------------------------------------------------------------
// Kernel 2: combine partials, compute phosphene params, windowed scatter.
// One warp per contact; grid = B_ * 125 CTAs of 8 warps.
// ---------------------------------------------------------------------------
__global__ void __launch_bounds__(256) scatter_kernel(const float* __restrict__ logits) {
    int warp = threadIdx.x >> 5;
    int lane = threadIdx.x & 31;
    int b = blockIdx.x / 125;
    int n = (blockIdx.x % 125) * 8 + warp;

    float wsum = 0.f, spol = 0.f, secc = 0.f;
    #pragma unroll
    for (int vs = 0; vs < VS_; vs++) {
        int idx = (vs * B_ + b) * NPAD + n;
        wsum += g_pw[idx];
        spol += g_pp[idx];
        secc += g_pc[idx];
    }

    float inv = 1.f / (wsum + 1e-8f);
    float pol = spol * inv;
    float ecc = secc * inv;
    float ang = pol * DEG2RAD_;
    float m = 17.3f * (1.f / (ecc + 0.75f) - 1.f / (ecc + 120.0f));
    float m_inv = 1.f / (fabsf(m) + 1e-8f);
    float psig = SPREAD_ * m_inv * 0.5f;
    float sv, cv;
    sincosf(ang, &sv, &cv);
    float cxp = ecc * cv * SCALED_ + 128.0f;
    float cyp = ecc * sv * SCALED_ + 128.0f;
    float size = fmaxf(psig * SCALED_, 1.0f);
    float validity = fminf(wsum, 1.0f);
    float lg = logits[b * N_ + n];
    float wf = validity / (1.f + __expf(-lg));

    // gaussian window scatter: beyond 6*size the tail < exp(-36) ~ 2e-16,
    // below fp32 resolution of the summed map.
    float rad = 6.0f * size;
    int x0 = max(0, (int)ceilf(cxp - rad));
    int x1 = min(H_ - 1, (int)floorf(cxp + rad));
    int y0 = max(0, (int)ceilf(cyp - rad));
    int y1 = min(H_ - 1, (int)floorf(cyp + rad));
    int wx = x1 - x0 + 1;
    int wy = y1 - y0 + 1;
    if (wx <= 0 || wy <= 0) return;
    int tot = wx * wy;
    float kk = -1.44269504f / (size * size + 1e-8f);   // exp2 folding
    float* mp = g_map + b * (H_ * H_);
    for (int p = lane; p < tot; p += 32) {
        int j = x0 + p % wx;
        int i = y0 + p / wx;
        float dx = (float)j - cxp;
        float dy = (float)i - cyp;
        float val = wf * fast_exp2(fmaf(dx, dx, dy * dy) * kk);
        atomicAdd(mp + i * H_ + j, val);
    }
}

// ---------------------------------------------------------------------------
// Kernel 3: per-batch max (wide grid). Map values >= 0, so float-bit int
// atomicMax is order-preserving.
// ---------------------------------------------------------------------------
__global__ void max_kernel() {
    int b   = blockIdx.x >> 4;            // 16 blocks per batch
    int blk = blockIdx.x & 15;
    const float* mp = g_map + b * (H_ * H_);
    int t = threadIdx.x;
    int lane = t & 31, warp = t >> 5;
    __shared__ float sred[8];

    float mx = 0.f;
    for (int i = blk * 4096 + t; i < (blk + 1) * 4096; i += 256)
        mx = fmaxf(mx, mp[i]);
    #pragma unroll
    for (int o = 16; o > 0; o >>= 1) mx = fmaxf(mx, __shfl_xor_sync(0xffffffffu, mx, o));
    if (lane == 0) sred[warp] = mx;
    __syncthreads();
    if (t == 0) {
        float m2 = sred[0];
        #pragma unroll
        for (int k = 1; k < 8; k++) m2 = fmaxf(m2, sred[k]);
        atomicMax(reinterpret_cast<int*>(&g_bmax[b]), __float_as_int(m2));
    }
}

// ---------------------------------------------------------------------------
// Kernel 4: rot90(k=1) + normalize into d_out via 32x32 smem-tiled transpose.
// out[b,i,j] = map[b, j*H + (255-i)] / (max + 1e-8)
// grid = B_ * 64 tiles; block = (32, 8).
// ---------------------------------------------------------------------------
__global__ void norm_kernel(float* __restrict__ out) {
    __shared__ float tile[32][33];
    int b  = blockIdx.x >> 6;
    int tl = blockIdx.x & 63;
    int ti = tl >> 3;            // out row tile
    int tj = tl & 7;             // out col tile
    int tc = 7 - ti;             // source col tile (c = 255 - i)
    int x = threadIdx.x;         // 0..31
    int y0 = threadIdx.y;        // 0..7

    const float* mp = g_map + b * (H_ * H_);
    float invm = 1.f / (g_bmax[b] + 1e-8f);

    // load: tile[r][x] = mp[(32*tj + r)*256 + 32*tc + x]   (coalesced in x)
    #pragma unroll
    for (int s = 0; s < 4; s++) {
        int r = y0 * 4 + s;
        tile[r][x] = mp[(32 * tj + r) * H_ + 32 * tc + x];
    }
    __syncthreads();

    // write: out[(32*ti + i')*256 + 32*tj + x] = tile[x][31 - i'] * invm
    float* ob = out + b * (H_ * H_);
    #pragma unroll
    for (int s = 0; s < 4; s++) {
        int ip = y0 * 4 + s;
        ob[(32 * ti + ip) * H_ + 32 * tj + x] = tile[x][31 - ip] * invm;
    }
}

// ---------------------------------------------------------------------------
// Input order (metadata): params, electrode_logits, v1_pos, v1_prf, start_loc,
//                         surf_dist_lut, alpha_grid, beta_grid, grid_template
// ---------------------------------------------------------------------------
extern "C" void kernel_launch(void* const* d_in, const int* in_sizes, int n_in,
                              void* d_out, int out_size) {
    const float* params   = (const float*)d_in[0];
    const float* logits   = (const float*)d_in[1];
    const float* v1_pos   = (const float*)d_in[2];
    const float* v1_prf   = (const float*)d_in[3];
    const float* startloc = (const float*)d_in[4];
    const float* lut      = (const float*)d_in[5];
    const float* agrid    = (const float*)d_in[6];
    const float* bgrid    = (const float*)d_in[7];
    const float* tmpl     = (const float*)d_in[8];
    float* out = (float*)d_out;

    init_kernel<<<513, 256>>>(v1_pos, v1_prf, params, startloc, lut, agrid, bgrid, tmpl);
    match_part_kernel<<<VS_ * B_ * CTA_PER_B, 256>>>(tmpl);
    scatter_kernel<<<B_ * 125, 256>>>(logits);
    max_kernel<<<B_ * 16, 256>>>();
    norm_kernel<<<B_ * 64, dim3(32, 8)>>>(out);
}